// round 1
// baseline (speedup 1.0000x reference)
#include <cuda_runtime.h>
#include <cstdint>

#define BATCH 16
#define HH 56
#define WW 56
#define EPSV 1e-5f

// ---------------- scratch (device globals; no allocation) ----------------
__device__ uint32_t g_Abits[BATCH * 8 * HH * WW];    // stage1 input bits  [b][w][y][x]
__device__ uint32_t g_Sbits[BATCH * 16 * HH * WW];   // stage2 input bits  [b][w][y][x] (w<8: out1, w>=8: idle)
__device__ float    g_Out1f[BATCH * 128 * HH * WW];  // out1 channels 0..127 (stage2 residual, even oc)
__device__ uint32_t g_W1b[72 * 256];                 // [k][oc], k=(w*3+r)*3+dx
__device__ uint32_t g_W2b[144 * 256];                // permuted for shuffle
__device__ int      g_NW1[9 * 256];                  // per-tap weight popcount [t][oc]
__device__ int      g_NW2[9 * 256];
__device__ float    g_alpha1[256], g_c1[256], g_alpha2[256], g_c2[256];

// ---------------- weight prep: bits + per-tap popcounts + folded BN -------
__global__ void prep_w1(const float* __restrict__ w1, const float* __restrict__ gm,
                        const float* __restrict__ bt, const float* __restrict__ mn,
                        const float* __restrict__ vr) {
    int oc = blockIdx.x;
    int c  = threadIdx.x;        // input channel 0..255
    int lane = c & 31, wi = c >> 5;
    __shared__ int nw[9];
    __shared__ float red[8];
    if (c < 9) nw[c] = 0;
    __syncthreads();
    float asum = 0.f;
#pragma unroll
    for (int r = 0; r < 3; r++)
#pragma unroll
        for (int dx = 0; dx < 3; dx++) {
            float v = w1[((oc * 256 + c) * 3 + r) * 3 + dx];
            asum += fabsf(v);
            unsigned word = __ballot_sync(0xffffffffu, v < 0.f);
            if (lane == 0) {
                int k = (wi * 3 + r) * 3 + dx;
                g_W1b[k * 256 + oc] = word;
                atomicAdd(&nw[r * 3 + dx], __popc(word));
            }
        }
    __syncthreads();
    if (c < 9) g_NW1[c * 256 + oc] = nw[c];
    for (int o = 16; o > 0; o >>= 1) asum += __shfl_xor_sync(0xffffffffu, asum, o);
    if (lane == 0) red[wi] = asum;
    __syncthreads();
    if (c == 0) {
        float s = 0.f;
#pragma unroll
        for (int i = 0; i < 8; i++) s += red[i];
        float scale = s / (256.f * 9.f);
        float inv = gm[oc] / sqrtf(vr[oc] + EPSV);
        g_alpha1[oc] = scale * inv;
        g_c1[oc] = bt[oc] - mn[oc] * inv;
    }
}

__global__ void prep_w2(const float* __restrict__ w2, const float* __restrict__ gm,
                        const float* __restrict__ bt, const float* __restrict__ mn,
                        const float* __restrict__ vr) {
    int oc = blockIdx.x;
    int c  = threadIdx.x;
    int lane = c & 31;
    __shared__ int nw[9];
    __shared__ float red[8];
    if (c < 9) nw[c] = 0;
    __syncthreads();
    float asum = 0.f;
    for (int it = 0; it < 2; it++) {
        int j  = it * 256 + c;                       // packed channel (post-shuffle order)
        int ic = (j < 256) ? (2 * j) : (2 * (j - 256) + 1);  // original w2 input channel
        int wi = j >> 5;
#pragma unroll
        for (int r = 0; r < 3; r++)
#pragma unroll
            for (int dx = 0; dx < 3; dx++) {
                float v = w2[((oc * 512 + ic) * 3 + r) * 3 + dx];
                asum += fabsf(v);
                unsigned word = __ballot_sync(0xffffffffu, v < 0.f);
                if (lane == 0) {
                    int k = (wi * 3 + r) * 3 + dx;
                    g_W2b[k * 256 + oc] = word;
                    atomicAdd(&nw[r * 3 + dx], __popc(word));
                }
            }
    }
    __syncthreads();
    if (c < 9) g_NW2[c * 256 + oc] = nw[c];
    for (int o = 16; o > 0; o >>= 1) asum += __shfl_xor_sync(0xffffffffu, asum, o);
    if (lane == 0) red[c >> 5] = asum;
    __syncthreads();
    if (c == 0) {
        float s = 0.f;
#pragma unroll
        for (int i = 0; i < 8; i++) s += red[i];
        float scale = s / (512.f * 9.f);
        float inv = gm[oc] / sqrtf(vr[oc] + EPSV);
        g_alpha2[oc] = scale * inv;
        g_c2[oc] = bt[oc] - mn[oc] * inv;
    }
}

// ---------------- input packing: sign bits of x_act and x_idle+bias ------
__global__ void pack_input(const float* __restrict__ x, const float* __restrict__ mb) {
    int n = blockIdx.x * blockDim.x + threadIdx.x;   // 0..50175
    if (n >= BATCH * HH * WW) return;
    int xw = n % (HH * WW);
    int b  = n / (HH * WW);
    const float* xp = x + (size_t)b * 512 * HH * WW + xw;
#pragma unroll 1
    for (int wi = 0; wi < 8; wi++) {
        uint32_t word = 0;
#pragma unroll
        for (int k = 0; k < 32; k++) {
            float v = __ldg(&xp[(size_t)(wi * 32 + k) * HH * WW]);
            word |= (v < 0.f ? 1u : 0u) << k;
        }
        g_Abits[(b * 8 + wi) * HH * WW + xw] = word;
    }
#pragma unroll 1
    for (int wi = 0; wi < 8; wi++) {
        uint32_t word = 0;
#pragma unroll
        for (int k = 0; k < 32; k++) {
            int ci = wi * 32 + k;
            float v = __ldg(&xp[(size_t)(256 + ci) * HH * WW]) + __ldg(&mb[ci]);
            word |= (v < 0.f ? 1u : 0u) << k;
        }
        g_Sbits[(b * 16 + (8 + wi)) * HH * WW + xw] = word;
    }
}

// ---------------- binarized conv (XOR+POPC GEMM) --------------------------
// Block: 256 threads; tile = 56 pixels (one row) x 128 oc. Thread: 7 px x 4 oc.
template <int WORDS, int STAGE>
__global__ __launch_bounds__(256) void binconv(const float* __restrict__ x,
                                               const float* __restrict__ mb,
                                               float* __restrict__ out) {
    constexpr int K = WORDS * 9;
    constexpr int CTOT = WORDS * 32;
    extern __shared__ uint32_t smem[];
    uint32_t* Ws = smem;               // [K][128]
    uint32_t* As = smem + K * 128;     // [WORDS*3][58], col = x'+1, halo = 0

    const uint32_t* Gb = (STAGE == 1) ? g_Abits : g_Sbits;
    const uint32_t* Wg = (STAGE == 1) ? g_W1b : g_W2b;

    int ocHalf = blockIdx.x;
    int y = blockIdx.y;
    int b = blockIdx.z;
    int tid = threadIdx.x;
    int og = tid & 31;       // oc-group lane
    int g  = tid >> 5;       // pixel-group (7 px each)

    for (int idx = tid; idx < K * 128; idx += 256) {
        int k = idx >> 7, o = idx & 127;
        Ws[idx] = Wg[k * 256 + ocHalf * 128 + o];
    }
    for (int idx = tid; idx < WORDS * 3 * 58; idx += 256) {
        int c = idx % 58;
        int wr = idx / 58;
        int r = wr % 3, w = wr / 3;
        int yy = y + r - 1;
        int xx = c - 1;
        uint32_t v = 0;
        if ((unsigned)yy < HH && (unsigned)xx < WW)
            v = Gb[((b * WORDS + w) * HH + yy) * WW + xx];
        As[wr * 58 + c] = v;
    }
    __syncthreads();

    int acc[7][4];
#pragma unroll
    for (int p = 0; p < 7; p++)
#pragma unroll
        for (int j = 0; j < 4; j++) acc[p][j] = 0;

#pragma unroll 1
    for (int w = 0; w < WORDS; w++) {
#pragma unroll
        for (int r = 0; r < 3; r++) {
            const uint32_t* arow = &As[(w * 3 + r) * 58 + 7 * g];
            uint32_t a[9];
#pragma unroll
            for (int i = 0; i < 9; i++) a[i] = arow[i];
#pragma unroll
            for (int dx = 0; dx < 3; dx++) {
                int k = (w * 3 + r) * 3 + dx;
                uint4 wv = *reinterpret_cast<const uint4*>(&Ws[k * 128 + og * 4]);
#pragma unroll
                for (int p = 0; p < 7; p++) {
                    uint32_t av = a[p + dx];
                    acc[p][0] += __popc(av ^ wv.x);
                    acc[p][1] += __popc(av ^ wv.y);
                    acc[p][2] += __popc(av ^ wv.z);
                    acc[p][3] += __popc(av ^ wv.w);
                }
            }
        }
    }

    // ---------------- epilogue ----------------
    int ocbase = ocHalf * 128 + og * 4;
    const float* Ag = (STAGE == 1) ? g_alpha1 : g_alpha2;
    const float* Cg = (STAGE == 1) ? g_c1 : g_c2;
    const int* NWg = (STAGE == 1) ? g_NW1 : g_NW2;
    float alpha[4], cc[4];
#pragma unroll
    for (int j = 0; j < 4; j++) { alpha[j] = __ldg(&Ag[ocbase + j]); cc[j] = __ldg(&Cg[ocbase + j]); }
    bool ybord = (y == 0) || (y == HH - 1);

    uint32_t nib[7];
#pragma unroll
    for (int p = 0; p < 7; p++) {
        int xx = 7 * g + p;
        bool bord = ybord || (xx == 0) || (xx == WW - 1);
        int nv = 9;
        int corr[4] = {0, 0, 0, 0};
        if (bord) {
#pragma unroll
            for (int t = 0; t < 9; t++) {
                int dy = t / 3 - 1, dx = t % 3 - 1;
                if ((unsigned)(y + dy) >= HH || (unsigned)(xx + dx) >= WW) {
                    nv--;
#pragma unroll
                    for (int j = 0; j < 4; j++) corr[j] += __ldg(&NWg[t * 256 + ocbase + j]);
                }
            }
        }
        uint32_t nb = 0;
#pragma unroll
        for (int j = 0; j < 4; j++) {
            int oc = ocbase + j;
            int dot = CTOT * nv - 2 * acc[p][j] + 2 * corr[j];
            float val = (float)dot * alpha[j] + cc[j];
            if (STAGE == 1) {
                val += __ldg(&x[(((size_t)b * 512 + oc) * HH + y) * WW + xx]);
            } else {
                float res;
                if ((oc & 1) == 0)
                    res = g_Out1f[(((size_t)b * 128 + (oc >> 1)) * HH + y) * WW + xx];
                else
                    res = __ldg(&x[(((size_t)b * 512 + 256 + (oc >> 1)) * HH + y) * WW + xx]) + __ldg(&mb[oc >> 1]);
                val += res;
            }
            val = fminf(fmaxf(val, -1.f), 1.f);
            if (STAGE == 1) {
                if (ocHalf == 0)
                    g_Out1f[(((size_t)b * 128 + oc) * HH + y) * WW + xx] = val;
                nb |= (val < 0.f ? 1u : 0u) << j;
            } else {
                out[(((size_t)b * 256 + oc) * HH + y) * WW + xx] = val;
            }
        }
        nib[p] = nb;
    }

    if (STAGE == 1) {
        // repack sign bits: Sbits word = 32 consecutive oc
        __syncthreads();
        uint32_t* stg = Ws;  // reuse (9216 words >= 56*32)
#pragma unroll
        for (int p = 0; p < 7; p++) stg[(7 * g + p) * 32 + og] = nib[p];
        __syncthreads();
        if (tid < 224) {
            int px = tid >> 2;
            int wl = tid & 3;
            uint32_t word = 0;
#pragma unroll
            for (int q = 0; q < 8; q++) word |= stg[px * 32 + wl * 8 + q] << (4 * q);
            g_Sbits[((b * 16 + (ocHalf * 4 + wl)) * HH + y) * WW + px] = word;
        }
    }
}

// ---------------- launch ----------------
extern "C" void kernel_launch(void* const* d_in, const int* in_sizes, int n_in,
                              void* d_out, int out_size) {
    const float* x      = (const float*)d_in[0];
    const float* w1     = (const float*)d_in[1];
    const float* w2     = (const float*)d_in[2];
    const float* gamma1 = (const float*)d_in[3];
    const float* beta1  = (const float*)d_in[4];
    const float* mean1  = (const float*)d_in[5];
    const float* var1   = (const float*)d_in[6];
    const float* gamma2 = (const float*)d_in[7];
    const float* beta2  = (const float*)d_in[8];
    const float* mean2  = (const float*)d_in[9];
    const float* var2   = (const float*)d_in[10];
    const float* mb     = (const float*)d_in[11];
    float* out = (float*)d_out;

    const int smem1 = (72 * 128 + 8 * 3 * 58) * 4;    // 42432 B
    const int smem2 = (144 * 128 + 16 * 3 * 58) * 4;  // 84864 B
    cudaFuncSetAttribute(binconv<8, 1>,  cudaFuncAttributeMaxDynamicSharedMemorySize, smem1);
    cudaFuncSetAttribute(binconv<16, 2>, cudaFuncAttributeMaxDynamicSharedMemorySize, smem2);

    prep_w1<<<256, 256>>>(w1, gamma1, beta1, mean1, var1);
    prep_w2<<<256, 256>>>(w2, gamma2, beta2, mean2, var2);
    pack_input<<<(BATCH * HH * WW + 255) / 256, 256>>>(x, mb);

    dim3 grid(2, HH, BATCH);
    binconv<8, 1><<<grid, 256, smem1>>>(x, mb, out);
    binconv<16, 2><<<grid, 256, smem2>>>(x, mb, out);
}

// round 2
// speedup vs baseline: 1.1160x; 1.1160x over previous
#include <cuda_runtime.h>
#include <cstdint>

#define BATCH 16
#define HH 56
#define WW 56
#define EPSV 1e-5f

// ---------------- scratch (device globals; no allocation) ----------------
__device__ uint32_t g_Abits[BATCH * 8 * HH * WW];    // stage1 input bits  [b][w][y][x]
__device__ uint32_t g_Sbits[BATCH * 16 * HH * WW];   // stage2 input bits  [b][w][y][x]
__device__ float    g_Out1f[BATCH * 128 * HH * WW];  // out1 channels 0..127
__device__ uint32_t g_W1b[72 * 256];                 // [k][oc]
__device__ uint32_t g_W2b[144 * 256];                // permuted for shuffle
__device__ int      g_NW1[9 * 256];
__device__ int      g_NW2[9 * 256];
__device__ float    g_alpha1[256], g_c1[256], g_alpha2[256], g_c2[256];

// ---------------- weight prep ----------------
__global__ void prep_w1(const float* __restrict__ w1, const float* __restrict__ gm,
                        const float* __restrict__ bt, const float* __restrict__ mn,
                        const float* __restrict__ vr) {
    int oc = blockIdx.x;
    int c  = threadIdx.x;
    int lane = c & 31, wi = c >> 5;
    __shared__ int nw[9];
    __shared__ float red[8];
    if (c < 9) nw[c] = 0;
    __syncthreads();
    float asum = 0.f;
#pragma unroll
    for (int r = 0; r < 3; r++)
#pragma unroll
        for (int dx = 0; dx < 3; dx++) {
            float v = w1[((oc * 256 + c) * 3 + r) * 3 + dx];
            asum += fabsf(v);
            unsigned word = __ballot_sync(0xffffffffu, v < 0.f);
            if (lane == 0) {
                int k = (wi * 3 + r) * 3 + dx;
                g_W1b[k * 256 + oc] = word;
                atomicAdd(&nw[r * 3 + dx], __popc(word));
            }
        }
    __syncthreads();
    if (c < 9) g_NW1[c * 256 + oc] = nw[c];
    for (int o = 16; o > 0; o >>= 1) asum += __shfl_xor_sync(0xffffffffu, asum, o);
    if (lane == 0) red[wi] = asum;
    __syncthreads();
    if (c == 0) {
        float s = 0.f;
#pragma unroll
        for (int i = 0; i < 8; i++) s += red[i];
        float scale = s / (256.f * 9.f);
        float inv = gm[oc] / sqrtf(vr[oc] + EPSV);
        g_alpha1[oc] = scale * inv;
        g_c1[oc] = bt[oc] - mn[oc] * inv;
    }
}

__global__ void prep_w2(const float* __restrict__ w2, const float* __restrict__ gm,
                        const float* __restrict__ bt, const float* __restrict__ mn,
                        const float* __restrict__ vr) {
    int oc = blockIdx.x;
    int c  = threadIdx.x;
    int lane = c & 31;
    __shared__ int nw[9];
    __shared__ float red[8];
    if (c < 9) nw[c] = 0;
    __syncthreads();
    float asum = 0.f;
    for (int it = 0; it < 2; it++) {
        int j  = it * 256 + c;
        int ic = (j < 256) ? (2 * j) : (2 * (j - 256) + 1);
        int wi = j >> 5;
#pragma unroll
        for (int r = 0; r < 3; r++)
#pragma unroll
            for (int dx = 0; dx < 3; dx++) {
                float v = w2[((oc * 512 + ic) * 3 + r) * 3 + dx];
                asum += fabsf(v);
                unsigned word = __ballot_sync(0xffffffffu, v < 0.f);
                if (lane == 0) {
                    int k = (wi * 3 + r) * 3 + dx;
                    g_W2b[k * 256 + oc] = word;
                    atomicAdd(&nw[r * 3 + dx], __popc(word));
                }
            }
    }
    __syncthreads();
    if (c < 9) g_NW2[c * 256 + oc] = nw[c];
    for (int o = 16; o > 0; o >>= 1) asum += __shfl_xor_sync(0xffffffffu, asum, o);
    if (lane == 0) red[c >> 5] = asum;
    __syncthreads();
    if (c == 0) {
        float s = 0.f;
#pragma unroll
        for (int i = 0; i < 8; i++) s += red[i];
        float scale = s / (512.f * 9.f);
        float inv = gm[oc] / sqrtf(vr[oc] + EPSV);
        g_alpha2[oc] = scale * inv;
        g_c2[oc] = bt[oc] - mn[oc] * inv;
    }
}

// ---------------- input packing ----------------
__global__ void pack_input(const float* __restrict__ x, const float* __restrict__ mb) {
    int n = blockIdx.x * blockDim.x + threadIdx.x;
    if (n >= BATCH * HH * WW) return;
    int xw = n % (HH * WW);
    int b  = n / (HH * WW);
    const float* xp = x + (size_t)b * 512 * HH * WW + xw;
#pragma unroll 1
    for (int wi = 0; wi < 8; wi++) {
        uint32_t word = 0;
#pragma unroll
        for (int k = 0; k < 32; k++) {
            float v = __ldg(&xp[(size_t)(wi * 32 + k) * HH * WW]);
            word |= (v < 0.f ? 1u : 0u) << k;
        }
        g_Abits[(b * 8 + wi) * HH * WW + xw] = word;
    }
#pragma unroll 1
    for (int wi = 0; wi < 8; wi++) {
        uint32_t word = 0;
#pragma unroll
        for (int k = 0; k < 32; k++) {
            int ci = wi * 32 + k;
            float v = __ldg(&xp[(size_t)(256 + ci) * HH * WW]) + __ldg(&mb[ci]);
            word |= (v < 0.f ? 1u : 0u) << k;
        }
        g_Sbits[(b * 16 + (8 + wi)) * HH * WW + xw] = word;
    }
}

// ---------------- binarized conv (XOR+POPC) --------------------------
// Block: 256 threads; tile = 56 px (one row) x 64 oc. Thread: 7 px x 2 oc.
// lane -> oc pair (main loop); writeout loops are lane -> px (coalesced).
template <int WORDS, int STAGE>
__global__ __launch_bounds__(256, 5) void binconv(const float* __restrict__ x,
                                                  const float* __restrict__ mb,
                                                  float* __restrict__ out) {
    constexpr int K = WORDS * 9;
    constexpr int CTOT = WORDS * 32;
    extern __shared__ uint32_t smem[];
    uint32_t* Ws = smem;                       // [K][64]  (reused post-mainloop)
    uint32_t* As = smem + K * 64;              // [WORDS*3][58]
    float*    Rs = (float*)(As + WORDS * 3 * 58); // stage1 only: [64][57] residual, becomes Vs
    float*    Vs = (STAGE == 1) ? Rs : (float*)Ws; // conv-result staging [64][57]
    uint32_t* stg = Ws;                        // stage1 sign-bit staging

    const uint32_t* Gb = (STAGE == 1) ? g_Abits : g_Sbits;
    const uint32_t* Wg = (STAGE == 1) ? g_W1b : g_W2b;

    int ocq = blockIdx.x;        // oc quarter (64 oc)
    int y = blockIdx.y;
    int b = blockIdx.z;
    int tid = threadIdx.x;
    int og = tid & 31;           // lane: oc pair index
    int g  = tid >> 5;           // warp: pixel group (7 px)

    // ---- cooperative loads ----
    for (int idx = tid; idx < K * 64; idx += 256) {
        int k = idx >> 6, o = idx & 63;
        Ws[idx] = Wg[k * 256 + ocq * 64 + o];
    }
    for (int idx = tid; idx < WORDS * 3 * 58; idx += 256) {
        int c = idx % 58;
        int wr = idx / 58;
        int r = wr % 3, w = wr / 3;
        int yy = y + r - 1;
        int xx = c - 1;
        uint32_t v = 0;
        if ((unsigned)yy < HH && (unsigned)xx < WW)
            v = Gb[((b * WORDS + w) * HH + yy) * WW + xx];
        As[wr * 58 + c] = v;
    }
    if (STAGE == 1) {
        // stage residual tile (coalesced), latency hidden under main loop
        for (int idx = tid; idx < 64 * WW; idx += 256) {
            int oc_l = idx / WW, px = idx % WW;
            Rs[oc_l * 57 + px] =
                __ldg(&x[(((size_t)b * 512 + ocq * 64 + oc_l) * HH + y) * WW + px]);
        }
    }
    __syncthreads();

    // ---- main loop ----
    int acc[7][2];
#pragma unroll
    for (int p = 0; p < 7; p++) { acc[p][0] = 0; acc[p][1] = 0; }

#pragma unroll 1
    for (int w = 0; w < WORDS; w++) {
#pragma unroll
        for (int r = 0; r < 3; r++) {
            const uint32_t* arow = &As[(w * 3 + r) * 58 + 7 * g];
            uint32_t a[9];
#pragma unroll
            for (int i = 0; i < 9; i++) a[i] = arow[i];
#pragma unroll
            for (int dx = 0; dx < 3; dx++) {
                int k = (w * 3 + r) * 3 + dx;
                uint2 wv = *reinterpret_cast<const uint2*>(&Ws[k * 64 + og * 2]);
#pragma unroll
                for (int p = 0; p < 7; p++) {
                    uint32_t av = a[p + dx];
                    acc[p][0] += __popc(av ^ wv.x);
                    acc[p][1] += __popc(av ^ wv.y);
                }
            }
        }
    }
    __syncthreads();   // Ws reads done; region reusable (Vs stage2 / stg stage1)

    // ---- epilogue: BN + (stage1: residual+clip+signs) -> smem staging ----
    int ocbase = ocq * 64 + og * 2;
    const float* Ag = (STAGE == 1) ? g_alpha1 : g_alpha2;
    const float* Cg = (STAGE == 1) ? g_c1 : g_c2;
    const int* NWg = (STAGE == 1) ? g_NW1 : g_NW2;
    float alpha[2], cc[2];
#pragma unroll
    for (int j = 0; j < 2; j++) { alpha[j] = __ldg(&Ag[ocbase + j]); cc[j] = __ldg(&Cg[ocbase + j]); }
    bool ybord = (y == 0) || (y == HH - 1);

#pragma unroll
    for (int p = 0; p < 7; p++) {
        int xx = 7 * g + p;
        bool bord = ybord || (xx == 0) || (xx == WW - 1);
        int nv = 9;
        int corr[2] = {0, 0};
        if (bord) {
#pragma unroll
            for (int t = 0; t < 9; t++) {
                int dy = t / 3 - 1, dx = t % 3 - 1;
                if ((unsigned)(y + dy) >= HH || (unsigned)(xx + dx) >= WW) {
                    nv--;
                    corr[0] += __ldg(&NWg[t * 256 + ocbase]);
                    corr[1] += __ldg(&NWg[t * 256 + ocbase + 1]);
                }
            }
        }
        if (STAGE == 1) {
            uint32_t sb = 0;
#pragma unroll
            for (int j = 0; j < 2; j++) {
                int dot = CTOT * nv - 2 * acc[p][j] + 2 * corr[j];
                float val = (float)dot * alpha[j] + cc[j];
                val += Rs[(og * 2 + j) * 57 + xx];
                val = fminf(fmaxf(val, -1.f), 1.f);
                Vs[(og * 2 + j) * 57 + xx] = val;     // in-place over Rs (same owner)
                sb |= (val < 0.f ? 1u : 0u) << j;
            }
            stg[xx * 32 + og] = sb;                    // in Ws region (post-sync)
        } else {
#pragma unroll
            for (int j = 0; j < 2; j++) {
                int dot = CTOT * nv - 2 * acc[p][j] + 2 * corr[j];
                Vs[(og * 2 + j) * 57 + xx] = (float)dot * alpha[j] + cc[j];
            }
        }
    }
    __syncthreads();

    // ---- coalesced writeout ----
    if (STAGE == 1) {
        if (ocq < 2) {  // float out1 needed only for oc < 128
            for (int idx = tid; idx < 64 * WW; idx += 256) {
                int oc_l = idx / WW, px = idx % WW;
                g_Out1f[(((size_t)b * 128 + ocq * 64 + oc_l) * HH + y) * WW + px] =
                    Vs[oc_l * 57 + px];
            }
        }
        if (tid < 2 * WW) {  // pack sign bits: 2 words of 32 oc per px
            int px = tid >> 1, wsel = tid & 1;
            uint32_t word = 0;
#pragma unroll
            for (int q = 0; q < 16; q++) {
                uint32_t v = stg[px * 32 + wsel * 16 + q];
                word |= (v & 1u) << (2 * q);
                word |= ((v >> 1) & 1u) << (2 * q + 1);
            }
            g_Sbits[((b * 16 + (ocq * 2 + wsel)) * HH + y) * WW + px] = word;
        }
    } else {
        for (int idx = tid; idx < 64 * WW; idx += 256) {
            int oc_l = idx / WW, px = idx % WW;
            int oc = ocq * 64 + oc_l;
            float v = Vs[oc_l * 57 + px];
            float res;
            if ((oc & 1) == 0)
                res = __ldg(&g_Out1f[(((size_t)b * 128 + (oc >> 1)) * HH + y) * WW + px]);
            else
                res = __ldg(&x[(((size_t)b * 512 + 256 + (oc >> 1)) * HH + y) * WW + px]) +
                      __ldg(&mb[oc >> 1]);
            v = fminf(fmaxf(v + res, -1.f), 1.f);
            out[(((size_t)b * 256 + oc) * HH + y) * WW + px] = v;
        }
    }
}

// ---------------- launch ----------------
extern "C" void kernel_launch(void* const* d_in, const int* in_sizes, int n_in,
                              void* d_out, int out_size) {
    const float* x      = (const float*)d_in[0];
    const float* w1     = (const float*)d_in[1];
    const float* w2     = (const float*)d_in[2];
    const float* gamma1 = (const float*)d_in[3];
    const float* beta1  = (const float*)d_in[4];
    const float* mean1  = (const float*)d_in[5];
    const float* var1   = (const float*)d_in[6];
    const float* gamma2 = (const float*)d_in[7];
    const float* beta2  = (const float*)d_in[8];
    const float* mean2  = (const float*)d_in[9];
    const float* var2   = (const float*)d_in[10];
    const float* mb     = (const float*)d_in[11];
    float* out = (float*)d_out;

    const int smem1 = (72 * 64 + 8 * 3 * 58 + 64 * 57) * 4;   // 38592 B
    const int smem2 = (144 * 64 + 16 * 3 * 58) * 4;           // 48000 B
    cudaFuncSetAttribute(binconv<8, 1>,  cudaFuncAttributeMaxDynamicSharedMemorySize, smem1);
    cudaFuncSetAttribute(binconv<16, 2>, cudaFuncAttributeMaxDynamicSharedMemorySize, smem2);

    prep_w1<<<256, 256>>>(w1, gamma1, beta1, mean1, var1);
    prep_w2<<<256, 256>>>(w2, gamma2, beta2, mean2, var2);
    pack_input<<<(BATCH * HH * WW + 255) / 256, 256>>>(x, mb);

    dim3 grid(4, HH, BATCH);
    binconv<8, 1><<<grid, 256, smem1>>>(x, mb, out);
    binconv<16, 2><<<grid, 256, smem2>>>(x, mb, out);
}

// round 3
// speedup vs baseline: 1.1334x; 1.0155x over previous
#include <cuda_runtime.h>
#include <cstdint>

#define BATCH 16
#define HH 56
#define WW 56
#define EPSV 1e-5f

// ---------------- scratch (device globals; no allocation) ----------------
__device__ uint32_t g_Abits[BATCH * 8 * HH * WW];    // stage1 input bits  [b][w][y][x]
__device__ uint32_t g_Sbits[BATCH * 16 * HH * WW];   // stage2 input bits  [b][w][y][x]
__device__ float    g_Out1f[BATCH * 128 * HH * WW];  // out1 channels 0..127
__device__ uint32_t g_W1b[72 * 256];                 // [k][oc]
__device__ uint32_t g_W2b[144 * 256];                // permuted for shuffle
__device__ int      g_NW1[9 * 256];
__device__ int      g_NW2[9 * 256];
__device__ float    g_alpha1[256], g_c1[256], g_alpha2[256], g_c2[256];

// ---------------- weight prep ----------------
__global__ void prep_w1(const float* __restrict__ w1, const float* __restrict__ gm,
                        const float* __restrict__ bt, const float* __restrict__ mn,
                        const float* __restrict__ vr) {
    int oc = blockIdx.x;
    int c  = threadIdx.x;
    int lane = c & 31, wi = c >> 5;
    __shared__ int nw[9];
    __shared__ float red[8];
    if (c < 9) nw[c] = 0;
    __syncthreads();
    float asum = 0.f;
#pragma unroll
    for (int r = 0; r < 3; r++)
#pragma unroll
        for (int dx = 0; dx < 3; dx++) {
            float v = w1[((oc * 256 + c) * 3 + r) * 3 + dx];
            asum += fabsf(v);
            unsigned word = __ballot_sync(0xffffffffu, v < 0.f);
            if (lane == 0) {
                int k = (wi * 3 + r) * 3 + dx;
                g_W1b[k * 256 + oc] = word;
                atomicAdd(&nw[r * 3 + dx], __popc(word));
            }
        }
    __syncthreads();
    if (c < 9) g_NW1[c * 256 + oc] = nw[c];
    for (int o = 16; o > 0; o >>= 1) asum += __shfl_xor_sync(0xffffffffu, asum, o);
    if (lane == 0) red[wi] = asum;
    __syncthreads();
    if (c == 0) {
        float s = 0.f;
#pragma unroll
        for (int i = 0; i < 8; i++) s += red[i];
        float scale = s / (256.f * 9.f);
        float inv = gm[oc] / sqrtf(vr[oc] + EPSV);
        g_alpha1[oc] = scale * inv;
        g_c1[oc] = bt[oc] - mn[oc] * inv;
    }
}

__global__ void prep_w2(const float* __restrict__ w2, const float* __restrict__ gm,
                        const float* __restrict__ bt, const float* __restrict__ mn,
                        const float* __restrict__ vr) {
    int oc = blockIdx.x;
    int c  = threadIdx.x;
    int lane = c & 31;
    __shared__ int nw[9];
    __shared__ float red[8];
    if (c < 9) nw[c] = 0;
    __syncthreads();
    float asum = 0.f;
    for (int it = 0; it < 2; it++) {
        int j  = it * 256 + c;
        int ic = (j < 256) ? (2 * j) : (2 * (j - 256) + 1);
        int wi = j >> 5;
#pragma unroll
        for (int r = 0; r < 3; r++)
#pragma unroll
            for (int dx = 0; dx < 3; dx++) {
                float v = w2[((oc * 512 + ic) * 3 + r) * 3 + dx];
                asum += fabsf(v);
                unsigned word = __ballot_sync(0xffffffffu, v < 0.f);
                if (lane == 0) {
                    int k = (wi * 3 + r) * 3 + dx;
                    g_W2b[k * 256 + oc] = word;
                    atomicAdd(&nw[r * 3 + dx], __popc(word));
                }
            }
    }
    __syncthreads();
    if (c < 9) g_NW2[c * 256 + oc] = nw[c];
    for (int o = 16; o > 0; o >>= 1) asum += __shfl_xor_sync(0xffffffffu, asum, o);
    if (lane == 0) red[c >> 5] = asum;
    __syncthreads();
    if (c == 0) {
        float s = 0.f;
#pragma unroll
        for (int i = 0; i < 8; i++) s += red[i];
        float scale = s / (512.f * 9.f);
        float inv = gm[oc] / sqrtf(vr[oc] + EPSV);
        g_alpha2[oc] = scale * inv;
        g_c2[oc] = bt[oc] - mn[oc] * inv;
    }
}

// ---------------- input packing ----------------
__global__ void pack_input(const float* __restrict__ x, const float* __restrict__ mb) {
    int n = blockIdx.x * blockDim.x + threadIdx.x;
    if (n >= BATCH * HH * WW) return;
    int xw = n % (HH * WW);
    int b  = n / (HH * WW);
    const float* xp = x + (size_t)b * 512 * HH * WW + xw;
#pragma unroll 1
    for (int wi = 0; wi < 8; wi++) {
        uint32_t word = 0;
#pragma unroll
        for (int k = 0; k < 32; k++) {
            float v = __ldg(&xp[(size_t)(wi * 32 + k) * HH * WW]);
            word |= (v < 0.f ? 1u : 0u) << k;
        }
        g_Abits[(b * 8 + wi) * HH * WW + xw] = word;
    }
#pragma unroll 1
    for (int wi = 0; wi < 8; wi++) {
        uint32_t word = 0;
#pragma unroll
        for (int k = 0; k < 32; k++) {
            int ci = wi * 32 + k;
            float v = __ldg(&xp[(size_t)(256 + ci) * HH * WW]) + __ldg(&mb[ci]);
            word |= (v < 0.f ? 1u : 0u) << k;
        }
        g_Sbits[(b * 16 + (8 + wi)) * HH * WW + xw] = word;
    }
}

__device__ __forceinline__ uint32_t maj3(uint32_t a, uint32_t b, uint32_t c) {
    return (a & b) | (b & c) | (a & c);   // single LOP3, LUT 0xE8
}

// ---------------- binarized conv (XOR + CSA popcount) ---------------------
// Block: 256 threads; tile = 56 px (one row) x 64 oc. Thread: 7 px x 2 oc.
// CSA over the 3 dx-taps: popc(x0)+popc(x1)+popc(x2) = popc(x0^x1^x2)+2*popc(maj).
template <int WORDS, int STAGE>
__global__ __launch_bounds__(256, 4) void binconv(const float* __restrict__ x,
                                                  const float* __restrict__ mb,
                                                  float* __restrict__ out) {
    constexpr int K = WORDS * 9;
    constexpr int CTOT = WORDS * 32;
    extern __shared__ uint32_t smem[];
    uint32_t* Ws = smem;                       // [K][64]  (reused post-mainloop)
    uint32_t* As = smem + K * 64;              // [WORDS*3][58]
    float*    Rs = (float*)(As + WORDS * 3 * 58); // stage1: [64][57] residual -> Vs
    float*    Vs = (STAGE == 1) ? Rs : (float*)Ws;
    uint32_t* stg = Ws;                        // stage1 sign-bit staging

    const uint32_t* Gb = (STAGE == 1) ? g_Abits : g_Sbits;
    const uint32_t* Wg = (STAGE == 1) ? g_W1b : g_W2b;

    int ocq = blockIdx.x;        // oc quarter (64 oc)
    int y = blockIdx.y;
    int b = blockIdx.z;
    int tid = threadIdx.x;
    int og = tid & 31;           // lane: oc pair index
    int g  = tid >> 5;           // warp: pixel group (7 px)

    // ---- cooperative loads ----
    for (int idx = tid; idx < K * 64; idx += 256) {
        int k = idx >> 6, o = idx & 63;
        Ws[idx] = Wg[k * 256 + ocq * 64 + o];
    }
    for (int idx = tid; idx < WORDS * 3 * 58; idx += 256) {
        int c = idx % 58;
        int wr = idx / 58;
        int r = wr % 3, w = wr / 3;
        int yy = y + r - 1;
        int xx = c - 1;
        uint32_t v = 0;
        if ((unsigned)yy < HH && (unsigned)xx < WW)
            v = Gb[((b * WORDS + w) * HH + yy) * WW + xx];
        As[wr * 58 + c] = v;
    }
    if (STAGE == 1) {
        for (int idx = tid; idx < 64 * WW; idx += 256) {
            int oc_l = idx / WW, px = idx % WW;
            Rs[oc_l * 57 + px] =
                __ldg(&x[(((size_t)b * 512 + ocq * 64 + oc_l) * HH + y) * WW + px]);
        }
    }
    __syncthreads();

    // ---- main loop ----
    int acc1[7][2], acc2[7][2];
#pragma unroll
    for (int p = 0; p < 7; p++) { acc1[p][0] = 0; acc1[p][1] = 0; acc2[p][0] = 0; acc2[p][1] = 0; }

#pragma unroll 1
    for (int w = 0; w < WORDS; w++) {
#pragma unroll
        for (int r = 0; r < 3; r++) {
            const uint32_t* arow = &As[(w * 3 + r) * 58 + 7 * g];
            uint32_t a[9];
#pragma unroll
            for (int i = 0; i < 9; i++) a[i] = arow[i];
            int k0 = (w * 3 + r) * 3;
            uint2 w0 = *reinterpret_cast<const uint2*>(&Ws[(k0 + 0) * 64 + og * 2]);
            uint2 w1 = *reinterpret_cast<const uint2*>(&Ws[(k0 + 1) * 64 + og * 2]);
            uint2 w2 = *reinterpret_cast<const uint2*>(&Ws[(k0 + 2) * 64 + og * 2]);
#pragma unroll
            for (int p = 0; p < 7; p++) {
                {
                    uint32_t x0 = a[p] ^ w0.x, x1 = a[p + 1] ^ w1.x, x2 = a[p + 2] ^ w2.x;
                    acc1[p][0] += __popc(x0 ^ x1 ^ x2);
                    acc2[p][0] += __popc(maj3(x0, x1, x2));
                }
                {
                    uint32_t x0 = a[p] ^ w0.y, x1 = a[p + 1] ^ w1.y, x2 = a[p + 2] ^ w2.y;
                    acc1[p][1] += __popc(x0 ^ x1 ^ x2);
                    acc2[p][1] += __popc(maj3(x0, x1, x2));
                }
            }
        }
    }
    __syncthreads();   // Ws reads done; region reusable

    // ---- epilogue ----
    int ocbase = ocq * 64 + og * 2;
    const float* Ag = (STAGE == 1) ? g_alpha1 : g_alpha2;
    const float* Cg = (STAGE == 1) ? g_c1 : g_c2;
    const int* NWg = (STAGE == 1) ? g_NW1 : g_NW2;
    float alpha[2], cc[2];
#pragma unroll
    for (int j = 0; j < 2; j++) { alpha[j] = __ldg(&Ag[ocbase + j]); cc[j] = __ldg(&Cg[ocbase + j]); }
    bool ybord = (y == 0) || (y == HH - 1);

#pragma unroll
    for (int p = 0; p < 7; p++) {
        int xx = 7 * g + p;
        bool bord = ybord || (xx == 0) || (xx == WW - 1);
        int nv = 9;
        int corr[2] = {0, 0};
        if (bord) {
#pragma unroll
            for (int t = 0; t < 9; t++) {
                int dy = t / 3 - 1, dx = t % 3 - 1;
                if ((unsigned)(y + dy) >= HH || (unsigned)(xx + dx) >= WW) {
                    nv--;
                    corr[0] += __ldg(&NWg[t * 256 + ocbase]);
                    corr[1] += __ldg(&NWg[t * 256 + ocbase + 1]);
                }
            }
        }
        if (STAGE == 1) {
            uint32_t sb = 0;
#pragma unroll
            for (int j = 0; j < 2; j++) {
                int ones = acc1[p][j] + 2 * acc2[p][j];
                int dot = CTOT * nv - 2 * ones + 2 * corr[j];
                float val = (float)dot * alpha[j] + cc[j];
                val += Rs[(og * 2 + j) * 57 + xx];
                val = fminf(fmaxf(val, -1.f), 1.f);
                Vs[(og * 2 + j) * 57 + xx] = val;
                sb |= (val < 0.f ? 1u : 0u) << j;
            }
            stg[xx * 32 + og] = sb;
        } else {
#pragma unroll
            for (int j = 0; j < 2; j++) {
                int ones = acc1[p][j] + 2 * acc2[p][j];
                int dot = CTOT * nv - 2 * ones + 2 * corr[j];
                Vs[(og * 2 + j) * 57 + xx] = (float)dot * alpha[j] + cc[j];
            }
        }
    }
    __syncthreads();

    // ---- coalesced writeout ----
    if (STAGE == 1) {
        if (ocq < 2) {
            for (int idx = tid; idx < 64 * WW; idx += 256) {
                int oc_l = idx / WW, px = idx % WW;
                g_Out1f[(((size_t)b * 128 + ocq * 64 + oc_l) * HH + y) * WW + px] =
                    Vs[oc_l * 57 + px];
            }
        }
        if (tid < 2 * WW) {
            int px = tid >> 1, wsel = tid & 1;
            uint32_t word = 0;
#pragma unroll
            for (int q = 0; q < 16; q++) {
                uint32_t v = stg[px * 32 + wsel * 16 + q];
                word |= (v & 1u) << (2 * q);
                word |= ((v >> 1) & 1u) << (2 * q + 1);
            }
            g_Sbits[((b * 16 + (ocq * 2 + wsel)) * HH + y) * WW + px] = word;
        }
    } else {
        for (int idx = tid; idx < 64 * WW; idx += 256) {
            int oc_l = idx / WW, px = idx % WW;
            int oc = ocq * 64 + oc_l;
            float v = Vs[oc_l * 57 + px];
            float res;
            if ((oc & 1) == 0)
                res = __ldg(&g_Out1f[(((size_t)b * 128 + (oc >> 1)) * HH + y) * WW + px]);
            else
                res = __ldg(&x[(((size_t)b * 512 + 256 + (oc >> 1)) * HH + y) * WW + px]) +
                      __ldg(&mb[oc >> 1]);
            v = fminf(fmaxf(v + res, -1.f), 1.f);
            out[(((size_t)b * 256 + oc) * HH + y) * WW + px] = v;
        }
    }
}

// ---------------- launch ----------------
extern "C" void kernel_launch(void* const* d_in, const int* in_sizes, int n_in,
                              void* d_out, int out_size) {
    const float* x      = (const float*)d_in[0];
    const float* w1     = (const float*)d_in[1];
    const float* w2     = (const float*)d_in[2];
    const float* gamma1 = (const float*)d_in[3];
    const float* beta1  = (const float*)d_in[4];
    const float* mean1  = (const float*)d_in[5];
    const float* var1   = (const float*)d_in[6];
    const float* gamma2 = (const float*)d_in[7];
    const float* beta2  = (const float*)d_in[8];
    const float* mean2  = (const float*)d_in[9];
    const float* var2   = (const float*)d_in[10];
    const float* mb     = (const float*)d_in[11];
    float* out = (float*)d_out;

    const int smem1 = (72 * 64 + 8 * 3 * 58 + 64 * 57) * 4;   // 38592 B
    const int smem2 = (144 * 64 + 16 * 3 * 58) * 4;           // 48000 B
    cudaFuncSetAttribute(binconv<8, 1>,  cudaFuncAttributeMaxDynamicSharedMemorySize, smem1);
    cudaFuncSetAttribute(binconv<16, 2>, cudaFuncAttributeMaxDynamicSharedMemorySize, smem2);

    prep_w1<<<256, 256>>>(w1, gamma1, beta1, mean1, var1);
    prep_w2<<<256, 256>>>(w2, gamma2, beta2, mean2, var2);
    pack_input<<<(BATCH * HH * WW + 255) / 256, 256>>>(x, mb);

    dim3 grid(4, HH, BATCH);
    binconv<8, 1><<<grid, 256, smem1>>>(x, mb, out);
    binconv<16, 2><<<grid, 256, smem2>>>(x, mb, out);
}

// round 4
// speedup vs baseline: 1.2253x; 1.0811x over previous
#include <cuda_runtime.h>
#include <cstdint>

#define BATCH 16
#define HH 56
#define WW 56
#define EPSV 1e-5f

// ---------------- scratch (device globals; no allocation) ----------------
__device__ uint32_t g_Abits[BATCH * 8 * HH * WW];    // stage1 input bits  [b][w][y][x]
__device__ uint32_t g_Sbits[BATCH * 16 * HH * WW];   // stage2 input bits  [b][w][y][x]
__device__ float    g_Out1f[BATCH * 128 * HH * WW];  // out1 channels 0..127
__device__ uint32_t g_W1b[72 * 256];                 // [k][oc]
__device__ uint32_t g_W2b[144 * 256];                // permuted for shuffle
__device__ int      g_NW1[9 * 256];
__device__ int      g_NW2[9 * 256];
__device__ float    g_alpha1[256], g_c1[256], g_alpha2[256], g_c2[256];

// ---------------- weight prep ----------------
__global__ void prep_w1(const float* __restrict__ w1, const float* __restrict__ gm,
                        const float* __restrict__ bt, const float* __restrict__ mn,
                        const float* __restrict__ vr) {
    int oc = blockIdx.x;
    int c  = threadIdx.x;
    int lane = c & 31, wi = c >> 5;
    __shared__ int nw[9];
    __shared__ float red[8];
    if (c < 9) nw[c] = 0;
    __syncthreads();
    float asum = 0.f;
#pragma unroll
    for (int r = 0; r < 3; r++)
#pragma unroll
        for (int dx = 0; dx < 3; dx++) {
            float v = w1[((oc * 256 + c) * 3 + r) * 3 + dx];
            asum += fabsf(v);
            unsigned word = __ballot_sync(0xffffffffu, v < 0.f);
            if (lane == 0) {
                int k = (wi * 3 + r) * 3 + dx;
                g_W1b[k * 256 + oc] = word;
                atomicAdd(&nw[r * 3 + dx], __popc(word));
            }
        }
    __syncthreads();
    if (c < 9) g_NW1[c * 256 + oc] = nw[c];
    for (int o = 16; o > 0; o >>= 1) asum += __shfl_xor_sync(0xffffffffu, asum, o);
    if (lane == 0) red[wi] = asum;
    __syncthreads();
    if (c == 0) {
        float s = 0.f;
#pragma unroll
        for (int i = 0; i < 8; i++) s += red[i];
        float scale = s / (256.f * 9.f);
        float inv = gm[oc] / sqrtf(vr[oc] + EPSV);
        g_alpha1[oc] = scale * inv;
        g_c1[oc] = bt[oc] - mn[oc] * inv;
    }
}

__global__ void prep_w2(const float* __restrict__ w2, const float* __restrict__ gm,
                        const float* __restrict__ bt, const float* __restrict__ mn,
                        const float* __restrict__ vr) {
    int oc = blockIdx.x;
    int c  = threadIdx.x;
    int lane = c & 31;
    __shared__ int nw[9];
    __shared__ float red[8];
    if (c < 9) nw[c] = 0;
    __syncthreads();
    float asum = 0.f;
    for (int it = 0; it < 2; it++) {
        int j  = it * 256 + c;
        int ic = (j < 256) ? (2 * j) : (2 * (j - 256) + 1);
        int wi = j >> 5;
#pragma unroll
        for (int r = 0; r < 3; r++)
#pragma unroll
            for (int dx = 0; dx < 3; dx++) {
                float v = w2[((oc * 512 + ic) * 3 + r) * 3 + dx];
                asum += fabsf(v);
                unsigned word = __ballot_sync(0xffffffffu, v < 0.f);
                if (lane == 0) {
                    int k = (wi * 3 + r) * 3 + dx;
                    g_W2b[k * 256 + oc] = word;
                    atomicAdd(&nw[r * 3 + dx], __popc(word));
                }
            }
    }
    __syncthreads();
    if (c < 9) g_NW2[c * 256 + oc] = nw[c];
    for (int o = 16; o > 0; o >>= 1) asum += __shfl_xor_sync(0xffffffffu, asum, o);
    if (lane == 0) red[c >> 5] = asum;
    __syncthreads();
    if (c == 0) {
        float s = 0.f;
#pragma unroll
        for (int i = 0; i < 8; i++) s += red[i];
        float scale = s / (512.f * 9.f);
        float inv = gm[oc] / sqrtf(vr[oc] + EPSV);
        g_alpha2[oc] = scale * inv;
        g_c2[oc] = bt[oc] - mn[oc] * inv;
    }
}

// ---------------- input packing ----------------
__global__ void pack_input(const float* __restrict__ x, const float* __restrict__ mb) {
    int n = blockIdx.x * blockDim.x + threadIdx.x;
    if (n >= BATCH * HH * WW) return;
    int xw = n % (HH * WW);
    int b  = n / (HH * WW);
    const float* xp = x + (size_t)b * 512 * HH * WW + xw;
#pragma unroll 1
    for (int wi = 0; wi < 8; wi++) {
        uint32_t word = 0;
#pragma unroll
        for (int k = 0; k < 32; k++) {
            float v = __ldg(&xp[(size_t)(wi * 32 + k) * HH * WW]);
            word |= (v < 0.f ? 1u : 0u) << k;
        }
        g_Abits[(b * 8 + wi) * HH * WW + xw] = word;
    }
#pragma unroll 1
    for (int wi = 0; wi < 8; wi++) {
        uint32_t word = 0;
#pragma unroll
        for (int k = 0; k < 32; k++) {
            int ci = wi * 32 + k;
            float v = __ldg(&xp[(size_t)(256 + ci) * HH * WW]) + __ldg(&mb[ci]);
            word |= (v < 0.f ? 1u : 0u) << k;
        }
        g_Sbits[(b * 16 + (8 + wi)) * HH * WW + xw] = word;
    }
}

__device__ __forceinline__ uint32_t maj3(uint32_t a, uint32_t b, uint32_t c) {
    return (a & b) | (b & c) | (a & c);   // single LOP3, LUT 0xE8
}

// ---------------- binarized conv (XOR + CSA popcount, packed accs) -------
// Block: 256 threads; tile = 56 px (one row) x 64 oc. Thread: 7 px x 2 oc.
// CSA: popc(x0)+popc(x1)+popc(x2) = popc(x0^x1^x2)+2*popc(maj).
// Packed accumulator: lo 16 bits = sum popc(xor3), hi 16 bits = sum popc(maj).
template <int WORDS, int STAGE, int MINB>
__global__ __launch_bounds__(256, MINB) void binconv(const float* __restrict__ x,
                                                     const float* __restrict__ mb,
                                                     float* __restrict__ out) {
    constexpr int K = WORDS * 9;
    constexpr int CTOT = WORDS * 32;
    extern __shared__ uint32_t smem[];
    uint32_t* Ws = smem;                       // [K][64]  (reused post-mainloop)
    uint32_t* As = smem + K * 64;              // [WORDS*3][58]
    float*    Rs = (float*)(As + WORDS * 3 * 58); // stage1: [64][57] residual -> Vs
    float*    Vs = (STAGE == 1) ? Rs : (float*)Ws;
    uint32_t* stg = Ws;                        // stage1 sign-bit staging

    const uint32_t* Gb = (STAGE == 1) ? g_Abits : g_Sbits;
    const uint32_t* Wg = (STAGE == 1) ? g_W1b : g_W2b;

    int ocq = blockIdx.x;        // oc quarter (64 oc)
    int y = blockIdx.y;
    int b = blockIdx.z;
    int tid = threadIdx.x;
    int og = tid & 31;           // lane: oc pair index
    int g  = tid >> 5;           // warp: pixel group (7 px)

    // ---- cooperative loads ----
    for (int idx = tid; idx < K * 64; idx += 256) {
        int k = idx >> 6, o = idx & 63;
        Ws[idx] = Wg[k * 256 + ocq * 64 + o];
    }
    for (int idx = tid; idx < WORDS * 3 * 58; idx += 256) {
        int c = idx % 58;
        int wr = idx / 58;
        int r = wr % 3, w = wr / 3;
        int yy = y + r - 1;
        int xx = c - 1;
        uint32_t v = 0;
        if ((unsigned)yy < HH && (unsigned)xx < WW)
            v = Gb[((b * WORDS + w) * HH + yy) * WW + xx];
        As[wr * 58 + c] = v;
    }
    if (STAGE == 1) {
        for (int idx = tid; idx < 64 * WW; idx += 256) {
            int oc_l = idx / WW, px = idx % WW;
            Rs[oc_l * 57 + px] =
                __ldg(&x[(((size_t)b * 512 + ocq * 64 + oc_l) * HH + y) * WW + px]);
        }
    }
    __syncthreads();

    // ---- main loop ----
    uint32_t acc[7][2];
#pragma unroll
    for (int p = 0; p < 7; p++) { acc[p][0] = 0; acc[p][1] = 0; }

#pragma unroll 1
    for (int w = 0; w < WORDS; w++) {
#pragma unroll
        for (int r = 0; r < 3; r++) {
            const uint32_t* arow = &As[(w * 3 + r) * 58 + 7 * g];
            uint32_t a[9];
#pragma unroll
            for (int i = 0; i < 9; i++) a[i] = arow[i];
            int k0 = (w * 3 + r) * 3;
            uint2 w0 = *reinterpret_cast<const uint2*>(&Ws[(k0 + 0) * 64 + og * 2]);
            uint2 w1 = *reinterpret_cast<const uint2*>(&Ws[(k0 + 1) * 64 + og * 2]);
            uint2 w2 = *reinterpret_cast<const uint2*>(&Ws[(k0 + 2) * 64 + og * 2]);
#pragma unroll
            for (int p = 0; p < 7; p++) {
                {
                    uint32_t x0 = a[p] ^ w0.x, x1 = a[p + 1] ^ w1.x, x2 = a[p + 2] ^ w2.x;
                    acc[p][0] = __popc(maj3(x0, x1, x2)) * 65536u + acc[p][0];  // IMAD (fma pipe)
                    acc[p][0] += __popc(x0 ^ x1 ^ x2);                          // IADD (alu)
                }
                {
                    uint32_t x0 = a[p] ^ w0.y, x1 = a[p + 1] ^ w1.y, x2 = a[p + 2] ^ w2.y;
                    acc[p][1] = __popc(maj3(x0, x1, x2)) * 65536u + acc[p][1];
                    acc[p][1] += __popc(x0 ^ x1 ^ x2);
                }
            }
        }
    }
    __syncthreads();   // Ws reads done; region reusable

    // ---- epilogue ----
    int ocbase = ocq * 64 + og * 2;
    const float* Ag = (STAGE == 1) ? g_alpha1 : g_alpha2;
    const float* Cg = (STAGE == 1) ? g_c1 : g_c2;
    const int* NWg = (STAGE == 1) ? g_NW1 : g_NW2;
    float alpha[2], cc[2];
#pragma unroll
    for (int j = 0; j < 2; j++) { alpha[j] = __ldg(&Ag[ocbase + j]); cc[j] = __ldg(&Cg[ocbase + j]); }
    bool ybord = (y == 0) || (y == HH - 1);

#pragma unroll
    for (int p = 0; p < 7; p++) {
        int xx = 7 * g + p;
        bool bord = ybord || (xx == 0) || (xx == WW - 1);
        int nv = 9;
        int corr[2] = {0, 0};
        if (bord) {
#pragma unroll
            for (int t = 0; t < 9; t++) {
                int dy = t / 3 - 1, dx = t % 3 - 1;
                if ((unsigned)(y + dy) >= HH || (unsigned)(xx + dx) >= WW) {
                    nv--;
                    corr[0] += __ldg(&NWg[t * 256 + ocbase]);
                    corr[1] += __ldg(&NWg[t * 256 + ocbase + 1]);
                }
            }
        }
        if (STAGE == 1) {
            uint32_t sb = 0;
#pragma unroll
            for (int j = 0; j < 2; j++) {
                int ones = (int)(acc[p][j] & 0xFFFFu) + 2 * (int)(acc[p][j] >> 16);
                int dot = CTOT * nv - 2 * ones + 2 * corr[j];
                float val = (float)dot * alpha[j] + cc[j];
                val += Rs[(og * 2 + j) * 57 + xx];
                val = fminf(fmaxf(val, -1.f), 1.f);
                Vs[(og * 2 + j) * 57 + xx] = val;
                sb |= (val < 0.f ? 1u : 0u) << j;
            }
            stg[xx * 32 + og] = sb;
        } else {
#pragma unroll
            for (int j = 0; j < 2; j++) {
                int ones = (int)(acc[p][j] & 0xFFFFu) + 2 * (int)(acc[p][j] >> 16);
                int dot = CTOT * nv - 2 * ones + 2 * corr[j];
                Vs[(og * 2 + j) * 57 + xx] = (float)dot * alpha[j] + cc[j];
            }
        }
    }
    __syncthreads();

    // ---- coalesced writeout ----
    if (STAGE == 1) {
        if (ocq < 2) {
            for (int idx = tid; idx < 64 * WW; idx += 256) {
                int oc_l = idx / WW, px = idx % WW;
                g_Out1f[(((size_t)b * 128 + ocq * 64 + oc_l) * HH + y) * WW + px] =
                    Vs[oc_l * 57 + px];
            }
        }
        if (tid < 2 * WW) {
            int px = tid >> 1, wsel = tid & 1;
            uint32_t word = 0;
#pragma unroll
            for (int q = 0; q < 16; q++) {
                uint32_t v = stg[px * 32 + wsel * 16 + q];
                word |= (v & 1u) << (2 * q);
                word |= ((v >> 1) & 1u) << (2 * q + 1);
            }
            g_Sbits[((b * 16 + (ocq * 2 + wsel)) * HH + y) * WW + px] = word;
        }
    } else {
        for (int idx = tid; idx < 64 * WW; idx += 256) {
            int oc_l = idx / WW, px = idx % WW;
            int oc = ocq * 64 + oc_l;
            float v = Vs[oc_l * 57 + px];
            float res;
            if ((oc & 1) == 0)
                res = __ldg(&g_Out1f[(((size_t)b * 128 + (oc >> 1)) * HH + y) * WW + px]);
            else
                res = __ldg(&x[(((size_t)b * 512 + 256 + (oc >> 1)) * HH + y) * WW + px]) +
                      __ldg(&mb[oc >> 1]);
            v = fminf(fmaxf(v + res, -1.f), 1.f);
            out[(((size_t)b * 256 + oc) * HH + y) * WW + px] = v;
        }
    }
}

// ---------------- launch ----------------
extern "C" void kernel_launch(void* const* d_in, const int* in_sizes, int n_in,
                              void* d_out, int out_size) {
    const float* x      = (const float*)d_in[0];
    const float* w1     = (const float*)d_in[1];
    const float* w2     = (const float*)d_in[2];
    const float* gamma1 = (const float*)d_in[3];
    const float* beta1  = (const float*)d_in[4];
    const float* mean1  = (const float*)d_in[5];
    const float* var1   = (const float*)d_in[6];
    const float* gamma2 = (const float*)d_in[7];
    const float* beta2  = (const float*)d_in[8];
    const float* mean2  = (const float*)d_in[9];
    const float* var2   = (const float*)d_in[10];
    const float* mb     = (const float*)d_in[11];
    float* out = (float*)d_out;

    const int smem1 = (72 * 64 + 8 * 3 * 58 + 64 * 57) * 4;   // 38592 B
    const int smem2 = (144 * 64 + 16 * 3 * 58) * 4;           // 48000 B
    cudaFuncSetAttribute(binconv<8, 1, 5>,  cudaFuncAttributeMaxDynamicSharedMemorySize, smem1);
    cudaFuncSetAttribute(binconv<16, 2, 4>, cudaFuncAttributeMaxDynamicSharedMemorySize, smem2);

    prep_w1<<<256, 256>>>(w1, gamma1, beta1, mean1, var1);
    prep_w2<<<256, 256>>>(w2, gamma2, beta2, mean2, var2);
    pack_input<<<(BATCH * HH * WW + 255) / 256, 256>>>(x, mb);

    dim3 grid(4, HH, BATCH);
    binconv<8, 1, 5><<<grid, 256, smem1>>>(x, mb, out);
    binconv<16, 2, 4><<<grid, 256, smem2>>>(x, mb, out);
}